// round 16
// baseline (speedup 1.0000x reference)
#include <cuda_runtime.h>
#include <cstdint>
#include <cstddef>
#include <math.h>

#define LVL   3
#define BSZ   128
#define T0    256
#define STOCH 128
#define DETER 1024
#define EMBED 512
#define OBS_D 512
#define G3    (3*DETER)   // 3072
#define NB    128          // persistent grid, 1 block/SM, all co-resident

typedef unsigned long long u64;
typedef unsigned int u32;

// ---------------------------------------------------------------------------
// Static device scratch. Transposed activations: X_T[k][m], m contiguous (128).
// ---------------------------------------------------------------------------
__device__ __align__(16) float g_hT [EMBED * BSZ];
__device__ __align__(16) float g_qhT[EMBED * BSZ];
__device__ __align__(16) float g_detT[2][DETER * BSZ];   // ping-pong by t&1
__device__ float g_dets1[BSZ * 64 * DETER];
__device__ float g_dets2[BSZ * 16 * DETER];
__device__ float g_pre_ctx[BSZ * 64 * EMBED];
__device__ float g_pre_obs[BSZ * T0 * EMBED];
__device__ float g_bvec[LVL][EMBED];
// Packed gates weights (per level): per (jblk,ch,kk,jl): {R,R,Z,Z,N,N,0,0}.
// chunk(jblk,ch) = 32kk x 8jl x 8 = 2048 floats = exact smem image.
__device__ __align__(16) float g_Wih_d[LVL][512  * 1024 * 8];
__device__ __align__(16) float g_Whh_d[LVL][1024 * 1024 * 8];
// Packed proj weights: per (nblk,ch32,kk,nl): {w,w}. chunk = 32x4x2 = 256 fl.
__device__ __align__(16) float g_Wq_d [LVL][1024 * 512 * 2];
__device__ __align__(16) float g_Wc_d [LVL][512 * 512 * 2];
__device__ unsigned int g_bar_count;
__device__ unsigned int g_bar_gen;

// ---------------------------------------------------------------------------
// Packed fp32 FMA (bit-exact fp32) + bulk-copy / mbarrier helpers
// ---------------------------------------------------------------------------
__device__ __forceinline__ void ffma2(u64& d, u64 a, u64 b) {
    asm("fma.rn.f32x2 %0, %1, %2, %0;" : "+l"(d) : "l"(a), "l"(b));
}
__device__ __forceinline__ float2 unpack2(u64 v) {
    float lo, hi;
    asm("mov.b64 {%0, %1}, %2;" : "=f"(lo), "=f"(hi) : "l"(v));
    return make_float2(lo, hi);
}
__device__ __forceinline__ void bulkcp(u32 dst, const float* src, u32 bytes, u32 mbar) {
    asm volatile(
        "cp.async.bulk.shared::cluster.global.mbarrier::complete_tx::bytes "
        "[%0], [%1], %2, [%3];"
        :: "r"(dst), "l"(src), "r"(bytes), "r"(mbar) : "memory");
}
__device__ __forceinline__ void mb_init(u32 mbar, u32 cnt) {
    asm volatile("mbarrier.init.shared.b64 [%0], %1;" :: "r"(mbar), "r"(cnt) : "memory");
}
__device__ __forceinline__ void mb_expect(u32 mbar, u32 bytes) {
    asm volatile("mbarrier.arrive.expect_tx.shared.b64 _, [%0], %1;"
                 :: "r"(mbar), "r"(bytes) : "memory");
}
__device__ __forceinline__ void mwait(u32 mbar, u32 parity) {
    u32 done;
    asm volatile(
        "{\n\t.reg .pred p;\n\t"
        "mbarrier.try_wait.parity.acquire.cta.shared::cta.b64 p, [%1], %2;\n\t"
        "selp.b32 %0, 1, 0, p;\n\t}"
        : "=r"(done) : "r"(mbar), "r"(parity) : "memory");
    if (!done) {
        asm volatile(
            "{\n\t.reg .pred P1;\n\t"
            "WAIT_LOOP_%=:\n\t"
            "mbarrier.try_wait.parity.acquire.cta.shared::cta.b64 P1, [%0], %1, 0x989680;\n\t"
            "@P1 bra.uni WAIT_DONE_%=;\n\t"
            "bra.uni WAIT_LOOP_%=;\n\t"
            "WAIT_DONE_%=:\n\t}"
            :: "r"(mbar), "r"(parity) : "memory");
    }
}
__device__ __forceinline__ void bar_g(int id) {
    asm volatile("bar.sync %0, 256;" :: "r"(id) : "memory");
}

// ---------------------------------------------------------------------------
// Software grid barrier. NB blocks co-resident. fence.proxy.async orders the
// generic-proxy activation writes before subsequent bulk-copy (async) reads.
// ---------------------------------------------------------------------------
__device__ __forceinline__ void grid_sync() {
    __syncthreads();
    if (threadIdx.x == 0) {
        volatile unsigned int* genp = &g_bar_gen;
        unsigned int g = *genp;
        __threadfence();
        unsigned int a = atomicAdd(&g_bar_count, 1u);
        if (a == NB - 1u) {
            atomicExch(&g_bar_count, 0u);
            __threadfence();
            atomicAdd(&g_bar_gen, 1u);
        } else {
            while (*genp == g) { }
        }
        __threadfence();
    }
    __syncthreads();
    if ((threadIdx.x & 255) == 0)
        asm volatile("fence.proxy.async;" ::: "memory");
}

// ---------------------------------------------------------------------------
// Pack kernels (layouts verified in R14/R15).
// ---------------------------------------------------------------------------
__device__ __forceinline__ void pack_gates(const float* src, float* dst,
                                           int K, long base, long stride)
{
    const int nch = K / 32;
    const long total = (long)K * 1024 * 4;   // pairs incl pad
    for (long o = base; o < total; o += stride) {
        int p   = (int)(o & 3);
        long r  = o >> 2;
        int jl  = (int)(r & 7);  r >>= 3;
        int kk  = (int)(r & 31); r >>= 5;
        int ch  = (int)(r % nch);
        int jblk = (int)(r / nch);
        float v = (p < 3)
            ? src[(size_t)(ch * 32 + kk) * G3 + p * DETER + jblk * 8 + jl]
            : 0.0f;
        *(float2*)&dst[o * 2] = make_float2(v, v);
    }
}

__device__ __forceinline__ void pack_proj(const float* src, float* dst,
                                          int K, long base, long stride)
{
    const int nch = K / 32;
    const long total = (long)K * EMBED;      // pairs
    for (long o = base; o < total; o += stride) {
        int nl  = (int)(o & 3);
        long r  = o >> 2;
        int kk  = (int)(r & 31); r >>= 5;
        int ch  = (int)(r % nch);
        int nblk = (int)(r / nch);
        float v = src[(size_t)(ch * 32 + kk) * EMBED + nblk * 4 + nl];
        *(float2*)&dst[o * 2] = make_float2(v, v);
    }
}

__global__ void pack_all_kernel(const float* __restrict__ Wih,
                                const float* __restrict__ Whh,
                                const float* __restrict__ Wq)
{
    const long base   = (long)blockIdx.x * blockDim.x + threadIdx.x;
    const long stride = (long)gridDim.x * blockDim.x;
    for (int l = 0; l < LVL; l++) {
        pack_gates(Wih + (size_t)l * EMBED * G3, g_Wih_d[l], EMBED, base, stride);
        pack_gates(Whh + (size_t)l * DETER * G3, g_Whh_d[l], DETER, base, stride);
        pack_proj (Wq  + (size_t)l * (DETER + OBS_D) * EMBED, g_Wq_d[l], DETER,
                   base, stride);
    }
}

// prep_all: Wcomb = Wqm @ Wp_sample computed element-wise (K=128 dots) straight
// into the packed proj layout (K=512), plus bvec. All 3 levels, one launch.
__global__ void prep_all_kernel(const float* __restrict__ Wqm,
                                const float* __restrict__ Wp,
                                const float* __restrict__ bp,
                                const float* __restrict__ bqm)
{
    const long idx    = (long)blockIdx.x * blockDim.x + threadIdx.x;
    const long stride = (long)gridDim.x * blockDim.x;

    if (idx < LVL * EMBED) {   // bvec
        int l = (int)(idx / EMBED), n = (int)(idx % EMBED);
        const float* Wp_l  = Wp  + (size_t)l * (STOCH + DETER) * EMBED;
        const float* bqm_l = bqm + (size_t)l * STOCH;
        float s = bp[(size_t)l * EMBED + n];
        for (int k = 0; k < STOCH; k++)
            s = fmaf(bqm_l[k], Wp_l[(size_t)k * EMBED + n], s);
        g_bvec[l][n] = s;
    }

    const long per = (long)EMBED * EMBED;          // 262144 pairs per level
    for (long o = idx; o < LVL * per; o += stride) {
        int l  = (int)(o / per);
        long r = o % per;
        int nl  = (int)(r & 3);  r >>= 2;
        int kk  = (int)(r & 31); r >>= 5;
        int ch  = (int)(r % 16);
        int nblk = (int)(r / 16);
        int k = ch * 32 + kk;              // qh index (row of Wcomb)
        int n = nblk * 4 + nl;             // h index
        const float* Wqm_l = Wqm + (size_t)l * EMBED * STOCH;
        const float* Wp_l  = Wp  + (size_t)l * (STOCH + DETER) * EMBED;
        float v = 0.f;
        for (int s = 0; s < STOCH; s++)
            v = fmaf(Wqm_l[(size_t)k * STOCH + s], Wp_l[(size_t)s * EMBED + n], v);
        *(float2*)&g_Wc_d[l][(o % per) * 2] = make_float2(v, v);
    }
}

// ---------------------------------------------------------------------------
// Dual precompute GEMM: z=0 -> pre_obs = obs @ Wq_obs (K=512)
//                       z=1 -> pre_ctx = dets_up @ Wp_ctx (K=1024)
// ---------------------------------------------------------------------------
__global__ __launch_bounds__(128) void dual_gemm_kernel(
    const float* __restrict__ obs, const float* __restrict__ WqObs,
    const float* __restrict__ up,  const float* __restrict__ WpCtx,
    int rows_obs, int rows_ctx)
{
    const float* A; const float* W; float* C; int K, lda, rows;
    if (blockIdx.z == 0) { A = obs; W = WqObs; C = g_pre_obs; K = OBS_D; lda = OBS_D; rows = rows_obs; }
    else                 { A = up;  W = WpCtx; C = g_pre_ctx; K = DETER; lda = DETER; rows = rows_ctx; }
    if ((int)blockIdx.y * 64 >= rows) return;

    constexpr int BM = 64, BN = 64, BK = 16, TM = 4, TN = 8;
    __shared__ float sA[BK][BM + 4];
    __shared__ float sW[BK][BN];

    const int tid  = threadIdx.x;
    const int tx   = tid & 7;
    const int ty   = tid >> 3;
    const int row0 = blockIdx.y * BM;
    const int col0 = blockIdx.x * BN;

    float acc[TM][TN];
    #pragma unroll
    for (int i = 0; i < TM; i++)
        #pragma unroll
        for (int j = 0; j < TN; j++) acc[i][j] = 0.0f;

    for (int k0 = 0; k0 < K; k0 += BK) {
        #pragma unroll
        for (int p = 0; p < 8; p++) {
            int i  = tid + p * 128;
            int kk = i & 15, r = i >> 4;
            sA[kk][r] = A[(size_t)(row0 + r) * lda + (k0 + kk)];
        }
        #pragma unroll
        for (int p = 0; p < 8; p++) {
            int i  = tid + p * 128;
            int kk = i >> 6, cc = i & 63;
            sW[kk][cc] = W[(size_t)(k0 + kk) * EMBED + (col0 + cc)];
        }
        __syncthreads();
        #pragma unroll
        for (int kk = 0; kk < BK; kk++) {
            float4 av = *(const float4*)&sA[kk][ty * TM];
            float4 w0 = *(const float4*)&sW[kk][tx * TN];
            float4 w1 = *(const float4*)&sW[kk][tx * TN + 4];
            float a[TM] = {av.x, av.y, av.z, av.w};
            float w[TN] = {w0.x, w0.y, w0.z, w0.w, w1.x, w1.y, w1.z, w1.w};
            #pragma unroll
            for (int i = 0; i < TM; i++)
                #pragma unroll
                for (int j = 0; j < TN; j++)
                    acc[i][j] = fmaf(a[i], w[j], acc[i][j]);
        }
        __syncthreads();
    }

    #pragma unroll
    for (int i = 0; i < TM; i++) {
        int m  = row0 + ty * TM + i;
        int n0 = col0 + tx * TN;
        float4 o0 = {acc[i][0], acc[i][1], acc[i][2], acc[i][3]};
        float4 o1 = {acc[i][4], acc[i][5], acc[i][6], acc[i][7]};
        *(float4*)&C[(size_t)m * EMBED + n0]     = o0;
        *(float4*)&C[(size_t)m * EMBED + n0 + 4] = o1;
    }
}

// ---------------------------------------------------------------------------
// Dynamic smem layout (float indices):
//   A bufs:  6 x 4096 @ 0       (gates: 0-3; proj g0: 0-2, g1: 3-5)
//   GW bufs: 4 x 2048 @ 24576   (gates W; proj W aliases this region)
//   PW(g):   3 x 256  @ 24576 + g*768
//   Red:     512      @ 32768
//   mbarriers @ byte 133120: gates 0-3, proj g0 4-6, proj g1 7-9
// ---------------------------------------------------------------------------
#define SM_A(k)     ((k) * 4096)
#define SM_GW(b)    (24576 + (b) * 2048)
#define SM_PW(g)    (24576 + (g) * 768)
#define SM_RED      32768
#define MB_OFF      133120
#define SMEM_BYTES  (133120 + 128)

// ---------------------------------------------------------------------------
// Merged gates pipeline (P2): 48 chunks (16 Wih + 32 Whh), depth 4.
// gph = per-barrier parity bitmask (bits 0-3), lives in a register.
// ---------------------------------------------------------------------------
__device__ __forceinline__ void gates_all(
    u64& aR, u64& aZ, u64& aNi, u64& aNh,
    const float* __restrict__ hT, const float* __restrict__ dOld,
    const float* __restrict__ Wih_b, const float* __restrict__ Whh_b,
    int nch, float* smem, u32 sb, u32& gph, int tid, int mb, int jl)
{
    const int pre = nch < 4 ? nch : 4;
    if (tid == 0) {
        for (int q = 0; q < pre; q++) {
            const float* Asrc = (q < 16) ? hT + (size_t)q * 4096
                                         : dOld + (size_t)(q - 16) * 4096;
            const float* Wsrc = (q < 16) ? Wih_b + (size_t)q * 2048
                                         : Whh_b + (size_t)(q - 16) * 2048;
            u32 m = sb + MB_OFF + q * 8;
            mb_expect(m, 24576);
            bulkcp(sb + SM_A(q) * 4,  Asrc, 16384, m);
            bulkcp(sb + SM_GW(q) * 4, Wsrc, 8192,  m);
        }
    }
    for (int ch = 0; ch < nch; ch++) {
        const int b = ch & 3;
        const u32 m = sb + MB_OFF + b * 8;
        mwait(m, (gph >> b) & 1u);
        gph ^= (1u << b);
        const float* sAc = smem + SM_A(b);
        const float* sWc = smem + SM_GW(b);
        if (ch < 16) {
            #pragma unroll
            for (int kk = 0; kk < 32; kk++) {
                u64 a = *(const u64*)(sAc + kk * 128 + mb);
                const float* wp = sWc + (kk * 8 + jl) * 8;
                ulonglong2 wRZ = *(const ulonglong2*)wp;
                u64 wN = *(const u64*)(wp + 4);
                ffma2(aR, a, wRZ.x);
                ffma2(aZ, a, wRZ.y);
                ffma2(aNi, a, wN);
            }
        } else {
            #pragma unroll
            for (int kk = 0; kk < 32; kk++) {
                u64 a = *(const u64*)(sAc + kk * 128 + mb);
                const float* wp = sWc + (kk * 8 + jl) * 8;
                ulonglong2 wRZ = *(const ulonglong2*)wp;
                u64 wN = *(const u64*)(wp + 4);
                ffma2(aR, a, wRZ.x);
                ffma2(aZ, a, wRZ.y);
                ffma2(aNh, a, wN);
            }
        }
        __syncthreads();
        if (ch + 4 < nch && tid == 0) {
            const int q = ch + 4;
            const float* Asrc = (q < 16) ? hT + (size_t)q * 4096
                                         : dOld + (size_t)(q - 16) * 4096;
            const float* Wsrc = (q < 16) ? Wih_b + (size_t)q * 2048
                                         : Whh_b + (size_t)(q - 16) * 2048;
            mb_expect(m, 24576);
            bulkcp(sb + SM_A(b) * 4,  Asrc, 16384, m);
            bulkcp(sb + SM_GW(b) * 4, Wsrc, 8192,  m);
        }
    }
    __syncthreads();
}

// ---------------------------------------------------------------------------
// Projection pipeline (P1/P3): per 256-thread group, depth 3.
// pph = per-barrier parity bitmask (bits 0-2) per group, register-resident.
// ---------------------------------------------------------------------------
__device__ __forceinline__ u64 proj_pass(
    const float* __restrict__ AT, const float* __restrict__ Wb, int nchg,
    float* smem, u32 sb, int aslot0, int wbase, int mb0, u32& pph,
    int lt, int mb, int nl, int gbar)
{
    const int pre = nchg < 3 ? nchg : 3;
    if (lt == 0) {
        for (int q = 0; q < pre; q++) {
            u32 m = sb + MB_OFF + (mb0 + q) * 8;
            mb_expect(m, 17408);
            bulkcp(sb + SM_A(aslot0 + q) * 4, AT + (size_t)q * 4096, 16384, m);
            bulkcp(sb + (wbase + q * 256) * 4, Wb + (size_t)q * 256, 1024, m);
        }
    }
    u64 acc = 0ull;
    int b = 0;
    for (int i = 0; i < nchg; i++) {
        const u32 m = sb + MB_OFF + (mb0 + b) * 8;
        mwait(m, (pph >> b) & 1u);
        pph ^= (1u << b);
        const float* sAc = smem + SM_A(aslot0 + b);
        const float* sWc = smem + wbase + b * 256;
        #pragma unroll
        for (int kk = 0; kk < 32; kk++) {
            u64 a = *(const u64*)(sAc + kk * 128 + mb);
            u64 w = *(const u64*)(sWc + (kk * 4 + nl) * 2);
            ffma2(acc, a, w);
        }
        bar_g(gbar);
        if (i + 3 < nchg && lt == 0) {
            mb_expect(m, 17408);
            bulkcp(sb + SM_A(aslot0 + b) * 4, AT + (size_t)(i + 3) * 4096, 16384, m);
            bulkcp(sb + (wbase + b * 256) * 4, Wb + (size_t)(i + 3) * 256, 1024, m);
        }
        b = (b == 2) ? 0 : b + 1;
    }
    bar_g(gbar);
    return acc;
}

// ---------------------------------------------------------------------------
// Persistent per-level scan. 128 blocks x 512 threads. 3 phases / step.
// ---------------------------------------------------------------------------
__global__ __launch_bounds__(512, 1) void level_kernel(
    float* __restrict__ dets, int T,
    int has_ctx, int T1,
    const float* __restrict__ Wih_p, const float* __restrict__ Whh_p,
    const float* __restrict__ Wq_p,  const float* __restrict__ Wc_p,
    const float* __restrict__ bih, const float* __restrict__ bhh,
    const float* __restrict__ bq,  const float* __restrict__ bp, int lvl)
{
    extern __shared__ __align__(16) float smem[];
    const u32 sb = (u32)__cvta_generic_to_shared(smem);

    const int tid  = threadIdx.x;
    const int bid  = blockIdx.x;
    const int rg   = tid >> 5;
    const int lane = tid & 31;
    const size_t ldd = (size_t)T * DETER;

    if (tid == 0) {
        #pragma unroll
        for (int k = 0; k < 10; k++) mb_init(sb + MB_OFF + k * 8, 1);
    }
    __syncthreads();

    // P2 coords: thread tile 2m x 1j (verified R14).
    const int mb = (rg & 7) * 16 + (lane & 7) * 2;
    const int jl = (rg >> 3) * 4 + (lane >> 3);
    const int j  = bid * 8 + jl;

    // P1/P3 coords: two 256-thread K-split groups (verified R14).
    const int g    = rg >> 3;
    const int lt   = tid & 255;
    const int nl   = lane >> 3;
    const int n    = bid * 4 + nl;
    const int gbar = g + 1;
    const int aslot0 = g * 3;
    const int wbase  = SM_PW(g);
    const int mb0    = 4 + g * 3;

    u64* Red = (u64*)(smem + SM_RED);
    const int slot = (mb >> 1) * 4 + nl;

    const float br   = bih[j] + bhh[j];
    const float bz   = bih[DETER + j] + bhh[DETER + j];
    const float bin_ = bih[2 * DETER + j];
    const float bhn  = bhh[2 * DETER + j];
    const float bp_n = bp[n];
    const float bv_n = g_bvec[lvl][n];
    const float bq_n = bq[n];

    const float* Wih_b = Wih_p + (size_t)bid * 16 * 2048;
    const float* Whh_b = Whh_p + (size_t)bid * 32 * 2048;
    const float* Wq_b  = Wq_p  + (size_t)bid * 32 * 256;
    const float* Wc_b  = Wc_p  + (size_t)bid * 16 * 256;

    u32 gph = 0, pph = 0;

    for (int t = 0; t < T; t++) {
        float* detT_new = g_detT[t & 1];
        const float* detT_old = g_detT[(t & 1) ^ 1];

        // ======================= P1: h_T ===================================
        {
            float pc0 = 0.f, pc1 = 0.f;
            if (has_ctx) {
                const int tt = t & (T1 - 1);
                pc0 = g_pre_ctx[((size_t)mb * T1 + tt) * EMBED + n];
                pc1 = g_pre_ctx[((size_t)(mb + 1) * T1 + tt) * EMBED + n];
            }
            u64 acc = 0ull;
            if (t > 0)
                acc = proj_pass(g_qhT + g * 32768, Wc_b + g * 2048, 8,
                                smem, sb, aslot0, wbase, mb0, pph,
                                lt, mb, nl, gbar);
            if (g == 1) Red[slot] = acc;
            __syncthreads();
            if (g == 0) {
                float2 v = unpack2(acc);
                float2 r = unpack2(Red[slot]);
                const float bb = (t == 0) ? bp_n : bv_n;
                float o0 = fmaxf(v.x + r.x + bb + pc0, 0.f);
                float o1 = fmaxf(v.y + r.y + bb + pc1, 0.f);
                *(float2*)&g_hT[n * 128 + mb] = make_float2(o0, o1);
            }
        }
        grid_sync();

        // ============ P2: merged gates (gi & gh) + GRU combine =============
        {
            u64 aR = 0ull, aZ = 0ull, aNi = 0ull, aNh = 0ull;
            float2 dold = make_float2(0.f, 0.f);
            if (t > 0)
                dold = *(const float2*)&detT_old[j * 128 + mb];

            gates_all(aR, aZ, aNi, aNh, g_hT, detT_old, Wih_b, Whh_b,
                      (t > 0) ? 48 : 16, smem, sb, gph, tid, mb, jl);

            float2 R = unpack2(aR), Z = unpack2(aZ);
            float2 Ni = unpack2(aNi), Nh = unpack2(aNh);
            float dn0, dn1;
            {
                float rr = 1.f / (1.f + expf(-(R.x + br)));
                float zz = 1.f / (1.f + expf(-(Z.x + bz)));
                float nn = tanhf(Ni.x + bin_ + rr * (Nh.x + bhn));
                dn0 = (1.f - zz) * nn + zz * dold.x;
            }
            {
                float rr = 1.f / (1.f + expf(-(R.y + br)));
                float zz = 1.f / (1.f + expf(-(Z.y + bz)));
                float nn = tanhf(Ni.y + bin_ + rr * (Nh.y + bhn));
                dn1 = (1.f - zz) * nn + zz * dold.y;
            }
            *(float2*)&detT_new[j * 128 + mb] = make_float2(dn0, dn1);
            dets[(size_t)mb * ldd + (size_t)t * DETER + j]       = dn0;
            dets[(size_t)(mb + 1) * ldd + (size_t)t * DETER + j] = dn1;
        }
        grid_sync();

        // ======================= P3: qh_T ==================================
        {
            const float po0 = g_pre_obs[((size_t)mb * T + t) * EMBED + n];
            const float po1 = g_pre_obs[((size_t)(mb + 1) * T + t) * EMBED + n];
            u64 acc = proj_pass(detT_new + g * 65536, Wq_b + g * 4096, 16,
                                smem, sb, aslot0, wbase, mb0, pph,
                                lt, mb, nl, gbar);
            if (g == 1) Red[slot] = acc;
            __syncthreads();
            if (g == 0) {
                float2 v = unpack2(acc);
                float2 r = unpack2(Red[slot]);
                float o0 = fmaxf(v.x + r.x + bq_n + po0, 0.f);
                float o1 = fmaxf(v.y + r.y + bq_n + po1, 0.f);
                *(float2*)&g_qhT[n * 128 + mb] = make_float2(o0, o1);
            }
        }
        grid_sync();
    }
}

// ---------------------------------------------------------------------------
// Host driver. Launch order: 0 pack_all, 1 prep_all, then per level
// {dual_gemm, level_kernel} -> level_kernel at indices 3, 5, 7.
// ---------------------------------------------------------------------------
extern "C" void kernel_launch(void* const* d_in, const int* in_sizes, int n_in,
                              void* d_out, int out_size)
{
    (void)in_sizes; (void)n_in; (void)out_size;
    const float* obs_arr[3] = {
        (const float*)d_in[0], (const float*)d_in[1], (const float*)d_in[2] };
    const float* Wp  = (const float*)d_in[3];
    const float* bp  = (const float*)d_in[4];
    const float* Wih = (const float*)d_in[5];
    const float* Whh = (const float*)d_in[6];
    const float* bih = (const float*)d_in[7];
    const float* bhh = (const float*)d_in[8];
    const float* Wq  = (const float*)d_in[9];
    const float* bq  = (const float*)d_in[10];
    const float* Wqm = (const float*)d_in[11];
    const float* bqm = (const float*)d_in[12];

    float *d1_, *d2_, *wih_d, *whh_d, *wq_d, *wc_d;
    cudaGetSymbolAddress((void**)&d1_, g_dets1);
    cudaGetSymbolAddress((void**)&d2_, g_dets2);
    cudaGetSymbolAddress((void**)&wih_d, g_Wih_d);
    cudaGetSymbolAddress((void**)&whh_d, g_Whh_d);
    cudaGetSymbolAddress((void**)&wq_d,  g_Wq_d);
    cudaGetSymbolAddress((void**)&wc_d,  g_Wc_d);

    static bool attr_set = false;
    if (!attr_set) {
        cudaFuncSetAttribute(level_kernel,
                             cudaFuncAttributeMaxDynamicSharedMemorySize,
                             SMEM_BYTES);
        attr_set = true;
    }

    const int Ts[3] = { T0, T0 / 4, T0 / 16 };   // 256, 64, 16
    float* dets[3]  = { (float*)d_out, d1_, d2_ };

    pack_all_kernel<<<2048, 256>>>(Wih, Whh, Wq);          // launch 0
    prep_all_kernel<<<1024, 256>>>(Wqm, Wp, bp, bqm);      // launch 1

    for (int level = LVL - 1; level >= 0; level--) {
        const int T = Ts[level];
        const float* Wp_l  = Wp  + (size_t)level * (STOCH + DETER) * EMBED;
        const float* bp_l  = bp  + (size_t)level * EMBED;
        const float* bih_l = bih + (size_t)level * G3;
        const float* bhh_l = bhh + (size_t)level * G3;
        const float* Wq_l  = Wq  + (size_t)level * (DETER + OBS_D) * EMBED;
        const float* bq_l  = bq  + (size_t)level * EMBED;

        const int has_ctx = (level < LVL - 1);
        const int T1 = has_ctx ? Ts[level + 1] : 1;
        const int rows_obs = BSZ * T;
        const int rows_ctx = has_ctx ? BSZ * T1 : 0;

        dim3 gr(EMBED / 64, rows_obs / 64, has_ctx ? 2 : 1);
        dual_gemm_kernel<<<gr, 128>>>(
            obs_arr[level], Wq_l + (size_t)DETER * EMBED,
            has_ctx ? dets[level + 1] : (const float*)d_out,
            Wp_l + (size_t)STOCH * EMBED,
            rows_obs, rows_ctx);

        level_kernel<<<NB, 512, SMEM_BYTES>>>(
            dets[level], T, has_ctx, T1,
            wih_d + (size_t)level * (512 * 1024 * 8),
            whh_d + (size_t)level * (1024 * 1024 * 8),
            wq_d  + (size_t)level * (1024 * 512 * 2),
            wc_d  + (size_t)level * (512 * 512 * 2),
            bih_l, bhh_l, bq_l, bp_l, level);
    }
}